// round 2
// baseline (speedup 1.0000x reference)
#include <cuda_runtime.h>
#include <cstdint>

#define HIDDEN    450
#define ATOM_FDIM 35
#define BOND_FDIM 5
#define MAX_NB    15

#define MAX_BONDS 40000
#define MAX_ATOMS 20000

// ---------------- scratch (static device globals; no runtime allocation) ----
__device__ float g_binput[(size_t)MAX_BONDS * HIDDEN];  // pre-relu bond input; reused as atom_hiddens at the end
__device__ float g_gmsg  [(size_t)MAX_BONDS * HIDDEN];  // graph_message
__device__ float g_nei   [(size_t)MAX_BONDS * HIDDEN];  // gathered neighbor sums

// ---------------- tf32 helpers ----------------------------------------------
__device__ __forceinline__ void split_tf32(float v, uint32_t& hi, uint32_t& lo) {
    uint32_t h;
    asm("cvt.rna.tf32.f32 %0, %1;" : "=r"(h) : "f"(v));
    float r = v - __uint_as_float(h);
    uint32_t l;
    asm("cvt.rna.tf32.f32 %0, %1;" : "=r"(l) : "f"(r));
    hi = h; lo = l;
}

__device__ __forceinline__ void mma8(float* c, const uint32_t* a, const uint32_t* b) {
    asm volatile(
        "mma.sync.aligned.m16n8k8.row.col.f32.tf32.tf32.f32 "
        "{%0,%1,%2,%3},{%4,%5,%6,%7},{%8,%9},{%0,%1,%2,%3};"
        : "+f"(c[0]), "+f"(c[1]), "+f"(c[2]), "+f"(c[3])
        : "r"(a[0]), "r"(a[1]), "r"(a[2]), "r"(a[3]), "r"(b[0]), "r"(b[1]));
}

// ---------------- tensor-core GEMM ------------------------------------------
// C[m][n] = epilogue( sum_k A[m][k] * W[n][k] ), 3xTF32 split for fp32 accuracy
// MODE 0: C = t, C2 = relu(t)                       (init layer,   K=40)
// MODE 1: C = relu(t + biasM[m][n])                 (msg layers,   K=450)
// MODE 2: C = relu(t + biasV[n]), A = concat(A1[:,:K1], A2)  (out, K=485)
#define BM 128
#define BN 64
#define BK 16
#define APAD 20    // row stride in smem; makes mma-fragment LDS conflict-free

template <int MODE>
__global__ __launch_bounds__(256)
void mma_gemm(const float* __restrict__ A, const float* __restrict__ A2, int K1,
              const float* __restrict__ W, int ldw,
              const float* __restrict__ biasM, const float* __restrict__ biasV,
              float* __restrict__ C, float* __restrict__ C2,
              int M, int N, int K)
{
    __shared__ uint32_t AsH[BM][APAD], AsL[BM][APAD];
    __shared__ uint32_t WsH[BN][APAD], WsL[BN][APAD];

    const int tid  = threadIdx.x;
    const int lane = tid & 31;
    const int wid  = tid >> 5;
    const int wm   = wid & 3;      // 4 warps along M
    const int wn   = wid >> 2;     // 2 warps along N
    const int row0 = blockIdx.y * BM;
    const int col0 = blockIdx.x * BN;

    float acc[2][4][4];
#pragma unroll
    for (int a = 0; a < 2; a++)
#pragma unroll
        for (int b = 0; b < 4; b++)
#pragma unroll
            for (int q = 0; q < 4; q++) acc[a][b][q] = 0.f;

    const int nK = (K + BK - 1) / BK;
    for (int kt = 0; kt < nK; kt++) {
        const int k0 = kt * BK;

        // ---- load + split A tile [BM x BK]
        if (MODE == 2) {
            // concat source, odd strides -> scalar loads
#pragma unroll
            for (int i = 0; i < 8; i++) {
                int idx = tid + i * 256;          // 0..2047
                int r = idx >> 4, c = idx & 15;
                int gr = row0 + r, gk = k0 + c;
                float v = 0.f;
                if (gr < M && gk < K)
                    v = (gk < K1) ? A[(size_t)gr * K1 + gk]
                                  : A2[(size_t)gr * HIDDEN + (gk - K1)];
                split_tf32(v, AsH[r][c], AsL[r][c]);
            }
        } else {
#pragma unroll
            for (int i = 0; i < 4; i++) {
                int idx = tid + i * 256;          // 0..1023 float2 slots
                int r = idx >> 3, c2 = idx & 7;
                int gr = row0 + r, gk = k0 + 2 * c2;
                float2 v = make_float2(0.f, 0.f);
                if (gr < M && gk < K)             // K even -> pair fully valid
                    v = *(const float2*)&A[(size_t)gr * K + gk];
                split_tf32(v.x, AsH[r][2 * c2],     AsL[r][2 * c2]);
                split_tf32(v.y, AsH[r][2 * c2 + 1], AsL[r][2 * c2 + 1]);
            }
        }

        // ---- load + split W tile [BN x BK]
        if (MODE == 2) {                           // ldw=485 odd -> scalar
#pragma unroll
            for (int i = 0; i < 4; i++) {
                int idx = tid + i * 256;           // 0..1023
                int r = idx >> 4, c = idx & 15;
                int gn = col0 + r, gk = k0 + c;
                float v = 0.f;
                if (gn < N && gk < K) v = W[(size_t)gn * ldw + gk];
                split_tf32(v, WsH[r][c], WsL[r][c]);
            }
        } else {
#pragma unroll
            for (int i = 0; i < 2; i++) {
                int idx = tid + i * 256;           // 0..511 float2 slots
                int r = idx >> 3, c2 = idx & 7;
                int gn = col0 + r, gk = k0 + 2 * c2;
                float2 v = make_float2(0.f, 0.f);
                if (gn < N && gk < K)
                    v = *(const float2*)&W[(size_t)gn * ldw + gk];
                split_tf32(v.x, WsH[r][2 * c2],     WsL[r][2 * c2]);
                split_tf32(v.y, WsH[r][2 * c2 + 1], WsL[r][2 * c2 + 1]);
            }
        }
        __syncthreads();

        // ---- mma over the two k=8 steps
#pragma unroll
        for (int ks = 0; ks < BK; ks += 8) {
            uint32_t aH[2][4], aL[2][4], bH[4][2], bL[4][2];
#pragma unroll
            for (int mt = 0; mt < 2; mt++) {
                int r = wm * 32 + mt * 16 + (lane >> 2);
                int c = ks + (lane & 3);
                aH[mt][0] = AsH[r][c];     aL[mt][0] = AsL[r][c];
                aH[mt][1] = AsH[r + 8][c]; aL[mt][1] = AsL[r + 8][c];
                aH[mt][2] = AsH[r][c + 4];     aL[mt][2] = AsL[r][c + 4];
                aH[mt][3] = AsH[r + 8][c + 4]; aL[mt][3] = AsL[r + 8][c + 4];
            }
#pragma unroll
            for (int nt = 0; nt < 4; nt++) {
                int n = wn * 32 + nt * 8 + (lane >> 2);
                int c = ks + (lane & 3);
                bH[nt][0] = WsH[n][c];     bL[nt][0] = WsL[n][c];
                bH[nt][1] = WsH[n][c + 4]; bL[nt][1] = WsL[n][c + 4];
            }
#pragma unroll
            for (int mt = 0; mt < 2; mt++)
#pragma unroll
                for (int nt = 0; nt < 4; nt++) {
                    mma8(acc[mt][nt], aH[mt], bL[nt]);   // hi*lo
                    mma8(acc[mt][nt], aL[mt], bH[nt]);   // lo*hi
                    mma8(acc[mt][nt], aH[mt], bH[nt]);   // hi*hi
                }
        }
        __syncthreads();
    }

    // ---- epilogue
#pragma unroll
    for (int mt = 0; mt < 2; mt++) {
        int rbase = row0 + wm * 32 + mt * 16 + (lane >> 2);
#pragma unroll
        for (int nt = 0; nt < 4; nt++) {
            int cbase = col0 + wn * 32 + nt * 8 + 2 * (lane & 3);
#pragma unroll
            for (int q = 0; q < 4; q++) {
                int r = rbase + ((q >= 2) ? 8 : 0);
                int c = cbase + (q & 1);
                if (r < M && c < N) {
                    float t = acc[mt][nt][q];
                    size_t o = (size_t)r * N + c;
                    if (MODE == 0) {
                        C[o]  = t;
                        C2[o] = t > 0.f ? t : 0.f;
                    } else if (MODE == 1) {
                        t += biasM[o];
                        C[o] = t > 0.f ? t : 0.f;
                    } else {
                        t += biasV[c];
                        C[o] = t > 0.f ? t : 0.f;
                    }
                }
            }
        }
    }
}

// ---------------- neighbor gather-sum ---------------------------------------
__global__ __launch_bounds__(256)
void gather_sum_kernel(const int* __restrict__ graph,
                       const float* __restrict__ tree, int n_mess,
                       const float* __restrict__ gmsg,
                       float* __restrict__ out)
{
    const int b = blockIdx.x;
    __shared__ const float* rows[MAX_NB];
    if (threadIdx.x < MAX_NB) {
        int id = graph[(size_t)b * MAX_NB + threadIdx.x];
        rows[threadIdx.x] = (id < n_mess) ? (tree + (size_t)id * HIDDEN)
                                          : (gmsg + (size_t)(id - n_mess) * HIDDEN);
    }
    __syncthreads();

    const int t = threadIdx.x;
    if (t < HIDDEN / 2) {              // 225 float2 per row
        float2 acc = make_float2(0.f, 0.f);
#pragma unroll
        for (int nb = 0; nb < MAX_NB; nb++) {
            float2 v = ((const float2*)rows[nb])[t];
            acc.x += v.x;
            acc.y += v.y;
        }
        ((float2*)(out + (size_t)b * HIDDEN))[t] = acc;
    }
}

// ---------------- per-molecule mean -----------------------------------------
__global__ __launch_bounds__(256)
void mol_mean_kernel(const float* __restrict__ ah, const int* __restrict__ mol_ids,
                     int n_atoms, float* __restrict__ out)
{
    const int m = blockIdx.x;
    __shared__ int s_start, s_end;
    if (threadIdx.x == 0) {
        int lo = 0, hi = n_atoms;
        while (lo < hi) { int mid = (lo + hi) >> 1; if (mol_ids[mid] <  m) lo = mid + 1; else hi = mid; }
        s_start = lo;
        lo = 0; hi = n_atoms;
        while (lo < hi) { int mid = (lo + hi) >> 1; if (mol_ids[mid] <= m) lo = mid + 1; else hi = mid; }
        s_end = lo;
    }
    __syncthreads();
    const int start = s_start;
    const int cnt   = s_end - s_start;
    const float inv = cnt > 0 ? 1.f / (float)cnt : 0.f;

    for (int h = threadIdx.x; h < HIDDEN; h += blockDim.x) {
        float s = 0.f;
        for (int a = 0; a < cnt; a++)
            s += ah[(size_t)(start + a) * HIDDEN + h];
        out[(size_t)m * HIDDEN + h] = s * inv;
    }
}

// ---------------- launch ----------------------------------------------------
extern "C" void kernel_launch(void* const* d_in, const int* in_sizes, int n_in,
                              void* d_out, int out_size)
{
    const float* fatoms = (const float*)d_in[0];
    const float* fbonds = (const float*)d_in[1];
    const int*   agraph = (const int*)d_in[2];
    const int*   bgraph = (const int*)d_in[3];
    const int*   mol_ids = (const int*)d_in[4];
    const float* tree   = (const float*)d_in[6];
    const float* W_i    = (const float*)d_in[7];
    const float* W_h    = (const float*)d_in[8];
    const float* W_o    = (const float*)d_in[9];
    const float* b_o    = (const float*)d_in[10];
    float* out = (float*)d_out;

    const int n_atoms = in_sizes[0] / ATOM_FDIM;
    const int n_bonds = in_sizes[1] / (ATOM_FDIM + BOND_FDIM);
    const int n_mess  = in_sizes[6] / HIDDEN;
    const int n_mols  = out_size / HIDDEN;
    const int IN_FDIM = ATOM_FDIM + BOND_FDIM;   // 40
    const int OUT_K   = ATOM_FDIM + HIDDEN;      // 485

    float *binput, *gmsg, *nei;
    cudaGetSymbolAddress((void**)&binput, g_binput);
    cudaGetSymbolAddress((void**)&gmsg,   g_gmsg);
    cudaGetSymbolAddress((void**)&nei,    g_nei);

    dim3 blk(256);
    dim3 grid_b((HIDDEN + BN - 1) / BN, (n_bonds + BM - 1) / BM);
    dim3 grid_a((HIDDEN + BN - 1) / BN, (n_atoms + BM - 1) / BM);

    // init: binput = fbonds @ W_i^T ; gmsg = relu(binput)
    mma_gemm<0><<<grid_b, blk>>>(fbonds, nullptr, 0, W_i, IN_FDIM,
                                 nullptr, nullptr, binput, gmsg,
                                 n_bonds, HIDDEN, IN_FDIM);

    // DEPTH-1 = 5 message-passing steps
    for (int it = 0; it < 5; it++) {
        gather_sum_kernel<<<n_bonds, blk>>>(bgraph, tree, n_mess, gmsg, nei);
        mma_gemm<1><<<grid_b, blk>>>(nei, nullptr, 0, W_h, HIDDEN,
                                     binput, nullptr, gmsg, nullptr,
                                     n_bonds, HIDDEN, HIDDEN);
    }

    // atom aggregation + output layer (atom_hiddens reuses g_binput)
    gather_sum_kernel<<<n_atoms, blk>>>(agraph, tree, n_mess, gmsg, nei);
    mma_gemm<2><<<grid_a, blk>>>(fatoms, nei, ATOM_FDIM, W_o, OUT_K,
                                 nullptr, b_o, binput, nullptr,
                                 n_atoms, HIDDEN, OUT_K);

    // per-molecule mean
    mol_mean_kernel<<<n_mols, blk>>>(binput, mol_ids, n_atoms, out);
}

// round 3
// speedup vs baseline: 1.3887x; 1.3887x over previous
#include <cuda_runtime.h>
#include <cstdint>

#define HIDDEN    450
#define ATOM_FDIM 35
#define MAX_NB    15

#define LDC     512          // fp32 activation matrices stride (covers 4x128 col blocks)
#define KB_PAD  464          // 450 -> 29*16
#define KI_PAD  48           // 40  -> 3*16
#define KO_PAD  496          // 485 -> 31*16
#define MB_PAD  40064        // 313*128
#define MA_PAD  20096        // 157*128
#define NW      512          // weight rows padded (>=450)

#define STAGES      3
#define STAGE_WORDS 10240    // 4 arrays * 128 rows * 20 words
#define SMEM_BYTES  (STAGES * STAGE_WORDS * 4)

// ---------------- scratch (device globals; .bss zero-init => padding is zero) ----
__device__ float    g_binput[(size_t)MB_PAD * LDC];
__device__ float    g_gmsg  [(size_t)MB_PAD * LDC];
__device__ uint32_t g_neiH[(size_t)MB_PAD * KB_PAD];
__device__ uint32_t g_neiL[(size_t)MB_PAD * KB_PAD];
__device__ uint32_t g_atH [(size_t)MA_PAD * KO_PAD];
__device__ uint32_t g_atL [(size_t)MA_PAD * KO_PAD];
__device__ uint32_t g_fbH [(size_t)MB_PAD * KI_PAD];
__device__ uint32_t g_fbL [(size_t)MB_PAD * KI_PAD];
__device__ uint32_t g_WiH[NW * KI_PAD], g_WiL[NW * KI_PAD];
__device__ uint32_t g_WhH[NW * KB_PAD], g_WhL[NW * KB_PAD];
__device__ uint32_t g_WoH[NW * KO_PAD], g_WoL[NW * KO_PAD];

// ---------------- tf32 helpers ----------------------------------------------
__device__ __forceinline__ void split_tf32(float v, uint32_t& hi, uint32_t& lo) {
    uint32_t h;
    asm("cvt.rna.tf32.f32 %0, %1;" : "=r"(h) : "f"(v));
    float r = v - __uint_as_float(h);
    uint32_t l;
    asm("cvt.rna.tf32.f32 %0, %1;" : "=r"(l) : "f"(r));
    hi = h; lo = l;
}

__device__ __forceinline__ void mma8(float* c, const uint32_t* a, const uint32_t* b) {
    asm volatile(
        "mma.sync.aligned.m16n8k8.row.col.f32.tf32.tf32.f32 "
        "{%0,%1,%2,%3},{%4,%5,%6,%7},{%8,%9},{%0,%1,%2,%3};"
        : "+f"(c[0]), "+f"(c[1]), "+f"(c[2]), "+f"(c[3])
        : "r"(a[0]), "r"(a[1]), "r"(a[2]), "r"(a[3]), "r"(b[0]), "r"(b[1]));
}

// ---------------- pre-split kernel ------------------------------------------
__global__ __launch_bounds__(256)
void split_matrix(const float* __restrict__ src, int ld_src, int rows, int cols,
                  uint32_t* __restrict__ dH, uint32_t* __restrict__ dL, int ld_dst)
{
    int i = blockIdx.x * blockDim.x + threadIdx.x;
    if (i >= rows * cols) return;
    int r = i / cols, c = i - r * cols;
    uint32_t h, l;
    split_tf32(src[(size_t)r * ld_src + c], h, l);
    size_t o = (size_t)r * ld_dst + c;
    dH[o] = h; dL[o] = l;
}

// ---------------- gather + split --------------------------------------------
// out[b][coff + :450] = tf32-split( sum_nb message[graph[b][nb]][:] )
__global__ __launch_bounds__(256)
void gather_split(const int* __restrict__ graph,
                  const float* __restrict__ tree, int n_mess,
                  const float* __restrict__ gmsg,
                  uint32_t* __restrict__ dH, uint32_t* __restrict__ dL,
                  int ld, int coff)
{
    const int b = blockIdx.x;
    __shared__ const float* rows[MAX_NB];
    if (threadIdx.x < MAX_NB) {
        int id = graph[(size_t)b * MAX_NB + threadIdx.x];
        rows[threadIdx.x] = (id < n_mess) ? (tree + (size_t)id * HIDDEN)
                                          : (gmsg + (size_t)(id - n_mess) * LDC);
    }
    __syncthreads();
    const int t = threadIdx.x;
    if (t < HIDDEN / 2) {
        float2 acc = make_float2(0.f, 0.f);
#pragma unroll
        for (int nb = 0; nb < MAX_NB; nb++) {
            float2 v = ((const float2*)rows[nb])[t];
            acc.x += v.x; acc.y += v.y;
        }
        uint32_t hx, lx, hy, ly;
        split_tf32(acc.x, hx, lx);
        split_tf32(acc.y, hy, ly);
        size_t o = (size_t)b * ld + coff + 2 * t;
        dH[o] = hx; dH[o + 1] = hy;
        dL[o] = lx; dL[o + 1] = ly;
    }
}

// ---------------- pipelined tensor-core GEMM --------------------------------
// C[m][n] = epi( sum_k A[m][k]*W[n][k] ), A/W pre-split tf32 hi/lo, ldc = LDC.
// MODE 0: C = t, C2 = relu(t)
// MODE 1: C = relu(t + biasM[m][n])
// MODE 2: C = relu(t + biasV[n])
template <int MODE>
__global__ __launch_bounds__(256)
void mma_gemm(const uint32_t* __restrict__ AH, const uint32_t* __restrict__ AL,
              const uint32_t* __restrict__ WH, const uint32_t* __restrict__ WL,
              int ldA, int nK,
              const float* __restrict__ biasM, const float* __restrict__ biasV,
              float* __restrict__ C, float* __restrict__ C2)
{
    extern __shared__ uint32_t sm[];
    const unsigned sbase = (unsigned)__cvta_generic_to_shared(sm);

    const int tid  = threadIdx.x;
    const int lane = tid & 31;
    const int wid  = tid >> 5;
    const int wm   = wid & 3;          // 4 warps along M (32 rows each)
    const int wn   = wid >> 2;         // 2 warps along N (64 cols each)
    const int row0 = blockIdx.y * 128;
    const int col0 = blockIdx.x * 128;

    float acc[2][8][4];
#pragma unroll
    for (int a = 0; a < 2; a++)
#pragma unroll
        for (int b = 0; b < 8; b++)
#pragma unroll
            for (int q = 0; q < 4; q++) acc[a][b][q] = 0.f;

    // stage issue: 2048 16B chunks, 8 per thread
    auto issue = [&](int stage, int kt) {
        const unsigned sb = sbase + stage * (STAGE_WORDS * 4);
        const int k0 = kt * 16;
#pragma unroll
        for (int i = 0; i < 8; i++) {
            int gc  = i * 256 + tid;
            int arr = gc >> 9;          // 0:AH 1:AL 2:WH 3:WL
            int cc  = gc & 511;
            int row = cc >> 2;
            int q   = cc & 3;
            const uint32_t* src = (arr == 0) ? AH : (arr == 1) ? AL : (arr == 2) ? WH : WL;
            int grow = ((arr < 2) ? row0 : col0) + row;
            const uint32_t* g = src + (size_t)grow * ldA + k0 + q * 4;
            unsigned d = sb + (unsigned)(arr * 2560 + row * 20 + q * 4) * 4u;
            asm volatile("cp.async.cg.shared.global [%0], [%1], 16;\n" :: "r"(d), "l"(g));
        }
        asm volatile("cp.async.commit_group;\n");
    };

    // prefetch
#pragma unroll
    for (int s = 0; s < STAGES - 1; s++) {
        if (s < nK) issue(s, s);
        else        asm volatile("cp.async.commit_group;\n");
    }

    for (int kt = 0; kt < nK; kt++) {
        asm volatile("cp.async.wait_group %0;\n" :: "n"(STAGES - 2));
        __syncthreads();

        // refill the oldest stage
        {
            int nxt = kt + STAGES - 1;
            if (nxt < nK) issue(nxt % STAGES, nxt);
            else          asm volatile("cp.async.commit_group;\n");
        }

        const int stage = kt % STAGES;
        const uint32_t* AHs = sm + stage * STAGE_WORDS;
        const uint32_t* ALs = AHs + 2560;
        const uint32_t* WHs = AHs + 5120;
        const uint32_t* WLs = AHs + 7680;

#pragma unroll
        for (int ks = 0; ks < 2; ks++) {
            const int kc = ks * 8 + (lane & 3);
            uint32_t aH[2][4], aL[2][4];
#pragma unroll
            for (int mt = 0; mt < 2; mt++) {
                int r = wm * 32 + mt * 16 + (lane >> 2);
                const uint32_t* pH = AHs + r * 20 + kc;
                aH[mt][0] = pH[0]; aH[mt][1] = pH[160]; aH[mt][2] = pH[4]; aH[mt][3] = pH[164];
                const uint32_t* pL = ALs + r * 20 + kc;
                aL[mt][0] = pL[0]; aL[mt][1] = pL[160]; aL[mt][2] = pL[4]; aL[mt][3] = pL[164];
            }
#pragma unroll
            for (int nt = 0; nt < 8; nt++) {
                int n = wn * 64 + nt * 8 + (lane >> 2);
                const uint32_t* pH = WHs + n * 20 + kc;
                uint32_t bH[2] = { pH[0], pH[4] };
                const uint32_t* pL = WLs + n * 20 + kc;
                uint32_t bL[2] = { pL[0], pL[4] };
#pragma unroll
                for (int mt = 0; mt < 2; mt++) {
                    mma8(acc[mt][nt], aH[mt], bL);
                    mma8(acc[mt][nt], aL[mt], bH);
                    mma8(acc[mt][nt], aH[mt], bH);
                }
            }
        }
    }
    __syncthreads();

    // epilogue (no bounds checks needed: rows/cols padded)
#pragma unroll
    for (int mt = 0; mt < 2; mt++) {
#pragma unroll
        for (int h = 0; h < 2; h++) {
            int r = row0 + wm * 32 + mt * 16 + (lane >> 2) + h * 8;
#pragma unroll
            for (int nt = 0; nt < 8; nt++) {
                int c = col0 + wn * 64 + nt * 8 + 2 * (lane & 3);
                float x = acc[mt][nt][h * 2 + 0];
                float y = acc[mt][nt][h * 2 + 1];
                size_t o = (size_t)r * LDC + c;
                if (MODE == 0) {
                    *(float2*)(C + o)  = make_float2(x, y);
                    *(float2*)(C2 + o) = make_float2(x > 0.f ? x : 0.f, y > 0.f ? y : 0.f);
                } else if (MODE == 1) {
                    float2 bm = *(const float2*)(biasM + o);
                    x += bm.x; y += bm.y;
                    *(float2*)(C + o) = make_float2(x > 0.f ? x : 0.f, y > 0.f ? y : 0.f);
                } else {
                    x += (c     < HIDDEN) ? biasV[c]     : 0.f;
                    y += (c + 1 < HIDDEN) ? biasV[c + 1] : 0.f;
                    *(float2*)(C + o) = make_float2(x > 0.f ? x : 0.f, y > 0.f ? y : 0.f);
                }
            }
        }
    }
}

// ---------------- per-molecule mean -----------------------------------------
__global__ __launch_bounds__(256)
void mol_mean_kernel(const float* __restrict__ ah, const int* __restrict__ mol_ids,
                     int n_atoms, float* __restrict__ out)
{
    const int m = blockIdx.x;
    __shared__ int s_start, s_end;
    if (threadIdx.x == 0) {
        int lo = 0, hi = n_atoms;
        while (lo < hi) { int mid = (lo + hi) >> 1; if (mol_ids[mid] <  m) lo = mid + 1; else hi = mid; }
        s_start = lo;
        lo = 0; hi = n_atoms;
        while (lo < hi) { int mid = (lo + hi) >> 1; if (mol_ids[mid] <= m) lo = mid + 1; else hi = mid; }
        s_end = lo;
    }
    __syncthreads();
    const int start = s_start;
    const int cnt   = s_end - s_start;
    const float inv = cnt > 0 ? 1.f / (float)cnt : 0.f;

    for (int h = threadIdx.x; h < HIDDEN; h += blockDim.x) {
        float s = 0.f;
        for (int a = 0; a < cnt; a++)
            s += ah[(size_t)(start + a) * LDC + h];
        out[(size_t)m * HIDDEN + h] = s * inv;
    }
}

// ---------------- launch ----------------------------------------------------
extern "C" void kernel_launch(void* const* d_in, const int* in_sizes, int n_in,
                              void* d_out, int out_size)
{
    const float* fatoms  = (const float*)d_in[0];
    const float* fbonds  = (const float*)d_in[1];
    const int*   agraph  = (const int*)d_in[2];
    const int*   bgraph  = (const int*)d_in[3];
    const int*   mol_ids = (const int*)d_in[4];
    const float* tree    = (const float*)d_in[6];
    const float* W_i     = (const float*)d_in[7];
    const float* W_h     = (const float*)d_in[8];
    const float* W_o     = (const float*)d_in[9];
    const float* b_o     = (const float*)d_in[10];
    float* out = (float*)d_out;

    const int n_atoms = in_sizes[0] / ATOM_FDIM;
    const int n_bonds = in_sizes[1] / (ATOM_FDIM + 5);
    const int n_mess  = in_sizes[6] / HIDDEN;
    const int n_mols  = out_size / HIDDEN;
    const int IN_FDIM = ATOM_FDIM + 5;       // 40
    const int OUT_K   = ATOM_FDIM + HIDDEN;  // 485

    float *binput, *gmsg;
    uint32_t *neiH, *neiL, *atH, *atL, *fbH, *fbL;
    uint32_t *WiH, *WiL, *WhH, *WhL, *WoH, *WoL;
    cudaGetSymbolAddress((void**)&binput, g_binput);
    cudaGetSymbolAddress((void**)&gmsg,   g_gmsg);
    cudaGetSymbolAddress((void**)&neiH,   g_neiH);
    cudaGetSymbolAddress((void**)&neiL,   g_neiL);
    cudaGetSymbolAddress((void**)&atH,    g_atH);
    cudaGetSymbolAddress((void**)&atL,    g_atL);
    cudaGetSymbolAddress((void**)&fbH,    g_fbH);
    cudaGetSymbolAddress((void**)&fbL,    g_fbL);
    cudaGetSymbolAddress((void**)&WiH,    g_WiH);
    cudaGetSymbolAddress((void**)&WiL,    g_WiL);
    cudaGetSymbolAddress((void**)&WhH,    g_WhH);
    cudaGetSymbolAddress((void**)&WhL,    g_WhL);
    cudaGetSymbolAddress((void**)&WoH,    g_WoH);
    cudaGetSymbolAddress((void**)&WoL,    g_WoL);

    cudaFuncSetAttribute(mma_gemm<0>, cudaFuncAttributeMaxDynamicSharedMemorySize, SMEM_BYTES);
    cudaFuncSetAttribute(mma_gemm<1>, cudaFuncAttributeMaxDynamicSharedMemorySize, SMEM_BYTES);
    cudaFuncSetAttribute(mma_gemm<2>, cudaFuncAttributeMaxDynamicSharedMemorySize, SMEM_BYTES);

    dim3 blk(256);
    const int mb = (n_bonds + 127) / 128;
    const int ma = (n_atoms + 127) / 128;
    dim3 grid_b(4, mb), grid_a(4, ma);

    // ---- pre-split inputs & weights
    split_matrix<<<(n_bonds * IN_FDIM + 255) / 256, blk>>>(fbonds, IN_FDIM, n_bonds, IN_FDIM, fbH, fbL, KI_PAD);
    split_matrix<<<(HIDDEN * IN_FDIM + 255) / 256, blk>>>(W_i, IN_FDIM, HIDDEN, IN_FDIM, WiH, WiL, KI_PAD);
    split_matrix<<<(HIDDEN * HIDDEN + 255) / 256, blk>>>(W_h, HIDDEN, HIDDEN, HIDDEN, WhH, WhL, KB_PAD);
    split_matrix<<<(HIDDEN * OUT_K + 255) / 256, blk>>>(W_o, OUT_K, HIDDEN, OUT_K, WoH, WoL, KO_PAD);
    split_matrix<<<(n_atoms * ATOM_FDIM + 255) / 256, blk>>>(fatoms, ATOM_FDIM, n_atoms, ATOM_FDIM, atH, atL, KO_PAD);

    // ---- init layer: binput = fbonds @ W_i^T ; gmsg = relu(binput)
    mma_gemm<0><<<grid_b, blk, SMEM_BYTES>>>(fbH, fbL, WiH, WiL, KI_PAD, KI_PAD / 16,
                                             nullptr, nullptr, binput, gmsg);

    // ---- 5 message-passing steps
    for (int it = 0; it < 5; it++) {
        gather_split<<<n_bonds, blk>>>(bgraph, tree, n_mess, gmsg, neiH, neiL, KB_PAD, 0);
        mma_gemm<1><<<grid_b, blk, SMEM_BYTES>>>(neiH, neiL, WhH, WhL, KB_PAD, KB_PAD / 16,
                                                 binput, nullptr, gmsg, nullptr);
    }

    // ---- atom aggregation + output layer (atom_hiddens reuses g_binput)
    gather_split<<<n_atoms, blk>>>(agraph, tree, n_mess, gmsg, atH, atL, KO_PAD, ATOM_FDIM);
    mma_gemm<2><<<grid_a, blk, SMEM_BYTES>>>(atH, atL, WoH, WoL, KO_PAD, KO_PAD / 16,
                                             nullptr, b_o, binput, nullptr);

    // ---- per-molecule mean
    mol_mean_kernel<<<n_mols, blk>>>(binput, mol_ids, n_atoms, out);
}